// round 2
// baseline (speedup 1.0000x reference)
#include <cuda_runtime.h>

#define T_STEPS 1000
#define BATCH   256
#define IN_DIM  3
#define H_DIM   512
#define OUT_DIM 2
#define TAIL    10
#define BETA    0.8f
#define THRESH  1.0f

// One block handles (batch b, quarter of H). 128 threads, one neuron each.
// Shared: full x trace for this batch row (1000*3 floats = 12 KB).
__global__ void __launch_bounds__(128, 8)
snn_scan_kernel(const float* __restrict__ x,
                const float* __restrict__ W1,
                float* __restrict__ spk_out)
{
    __shared__ float xs[T_STEPS * IN_DIM];

    const int b   = blockIdx.x;
    const int tid = threadIdx.x;

    // Cooperative load of x_seq[:, b, :] into shared.
    // x layout: [T, B, IN] -> x[(t*BATCH + b)*IN + c]
    for (int i = tid; i < T_STEPS * IN_DIM; i += 128) {
        int t = i / IN_DIM;
        int c = i - t * IN_DIM;
        xs[i] = x[(t * BATCH + b) * IN_DIM + c];
    }

    const int h = blockIdx.y * 128 + tid;
    const float w0 = W1[h * IN_DIM + 0];
    const float w1 = W1[h * IN_DIM + 1];
    const float w2 = W1[h * IN_DIM + 2];

    __syncthreads();

    float mem = 0.0f;
    float* op = spk_out + (size_t)b * H_DIM + h;

#pragma unroll 4
    for (int t = 0; t < T_STEPS; ++t) {
        const float x0 = xs[3 * t + 0];
        const float x1 = xs[3 * t + 1];
        const float x2 = xs[3 * t + 2];
        // cur = x0*w0 + x1*w1 + x2*w2, left-to-right fma accumulation
        float cur = fmaf(x2, w2, fmaf(x1, w1, x0 * w0));
        // reset from PREVIOUS mem (zero-reset), then integrate
        float m = fmaf(BETA, mem, cur);
        m = (mem > THRESH) ? 0.0f : m;
        mem = m;
        // spike = heaviside(m - 1)
        op[(size_t)t * (BATCH * H_DIM)] = (m > THRESH) ? 1.0f : 0.0f;
    }
}

// Readout: avg_out[b,o] = mean over last 10 steps of sigmoid(spk[t,b,:] . W2[o,:])
// One block per batch row, 128 threads.
__global__ void __launch_bounds__(128)
readout_kernel(const float* __restrict__ spk,
               const float* __restrict__ W2,
               float* __restrict__ avg_out)
{
    const int b   = blockIdx.x;
    const int tid = threadIdx.x;
    const int lane = tid & 31;

    float acc[TAIL][OUT_DIM];
#pragma unroll
    for (int t = 0; t < TAIL; ++t) {
        acc[t][0] = 0.0f;
        acc[t][1] = 0.0f;
    }

    for (int h = tid; h < H_DIM; h += 128) {
        const float wa = W2[h];            // o = 0
        const float wb = W2[H_DIM + h];    // o = 1
#pragma unroll
        for (int t = 0; t < TAIL; ++t) {
            const size_t idx = ((size_t)(T_STEPS - TAIL + t) * BATCH + b) * H_DIM + h;
            const float s = spk[idx];
            acc[t][0] = fmaf(s, wa, acc[t][0]);
            acc[t][1] = fmaf(s, wb, acc[t][1]);
        }
    }

    __shared__ float sums[TAIL * OUT_DIM];
    if (tid < TAIL * OUT_DIM) sums[tid] = 0.0f;
    __syncthreads();

#pragma unroll
    for (int t = 0; t < TAIL; ++t) {
#pragma unroll
        for (int o = 0; o < OUT_DIM; ++o) {
            float v = acc[t][o];
            // warp tree reduce
            v += __shfl_down_sync(0xFFFFFFFFu, v, 16);
            v += __shfl_down_sync(0xFFFFFFFFu, v, 8);
            v += __shfl_down_sync(0xFFFFFFFFu, v, 4);
            v += __shfl_down_sync(0xFFFFFFFFu, v, 2);
            v += __shfl_down_sync(0xFFFFFFFFu, v, 1);
            if (lane == 0) atomicAdd(&sums[t * OUT_DIM + o], v);
        }
    }
    __syncthreads();

    if (tid < OUT_DIM) {
        float a = 0.0f;
#pragma unroll
        for (int t = 0; t < TAIL; ++t) {
            const float z = sums[t * OUT_DIM + tid];
            a += 1.0f / (1.0f + __expf(-z));
        }
        avg_out[b * OUT_DIM + tid] = a * (1.0f / (float)TAIL);
    }
}

extern "C" void kernel_launch(void* const* d_in, const int* in_sizes, int n_in,
                              void* d_out, int out_size)
{
    const float* x  = (const float*)d_in[0];   // [T, B, IN]
    const float* W1 = (const float*)d_in[1];   // [H, IN]
    const float* W2 = (const float*)d_in[2];   // [OUT, H]
    float* out = (float*)d_out;

    // out = [ spk_rec (T*B*H floats) | avg_out (B*OUT floats) ]
    float* spk = out;
    float* avg = out + (size_t)T_STEPS * BATCH * H_DIM;

    dim3 grid(BATCH, H_DIM / 128);
    snn_scan_kernel<<<grid, 128>>>(x, W1, spk);
    readout_kernel<<<BATCH, 128>>>(spk, W2, avg);
}

// round 7
// speedup vs baseline: 1.1776x; 1.1776x over previous
#include <cuda_runtime.h>

#define T_STEPS 1000
#define BATCH   256
#define IN_DIM  3
#define H_DIM   512
#define OUT_DIM 2
#define TAIL    10
#define T_MAIN  (T_STEPS - TAIL)
#define BETA    0.8f
#define THRESH  1.0f

// One block per batch row. 256 threads, each owns 2 consecutive neurons.
// Full H=512 in one block -> readout fused (block-local reduction).
__global__ void __launch_bounds__(256, 4)
snn_fused_kernel(const float* __restrict__ x,
                 const float* __restrict__ W1,
                 const float* __restrict__ W2,
                 float* __restrict__ spk_out,
                 float* __restrict__ avg_out)
{
    __shared__ float xs[T_STEPS * IN_DIM];      // 12 KB: this batch row's x trace
    __shared__ float sums[TAIL * OUT_DIM];

    const int b   = blockIdx.x;
    const int tid = threadIdx.x;
    const int lane = tid & 31;

    // Cooperative load of x_seq[:, b, :]  (x layout [T, B, IN])
    for (int i = tid; i < T_STEPS * IN_DIM; i += 256) {
        int t = i / IN_DIM;
        int c = i - t * IN_DIM;
        xs[i] = x[(t * BATCH + b) * IN_DIM + c];
    }
    if (tid < TAIL * OUT_DIM) sums[tid] = 0.0f;

    const int h = tid * 2;
    const float w00 = W1[h * IN_DIM + 0];
    const float w01 = W1[h * IN_DIM + 1];
    const float w02 = W1[h * IN_DIM + 2];
    const float w10 = W1[h * IN_DIM + 3];
    const float w11 = W1[h * IN_DIM + 4];
    const float w12 = W1[h * IN_DIM + 5];

    __syncthreads();

    float m0 = 0.0f, m1 = 0.0f;
    float2* op = (float2*)(spk_out + (size_t)b * H_DIM + h);
    const size_t stride2 = (size_t)BATCH * H_DIM / 2;   // float2 units per timestep

    // ---- main scan (no readout) ----
#pragma unroll 4
    for (int t = 0; t < T_MAIN; ++t) {
        const float x0 = xs[3 * t + 0];
        const float x1 = xs[3 * t + 1];
        const float x2 = xs[3 * t + 2];
        float c0 = fmaf(x2, w02, fmaf(x1, w01, x0 * w00));
        float c1 = fmaf(x2, w12, fmaf(x1, w11, x0 * w10));
        float n0 = fmaf(BETA, m0, c0);  n0 = (m0 > THRESH) ? 0.0f : n0;
        float n1 = fmaf(BETA, m1, c1);  n1 = (m1 > THRESH) ? 0.0f : n1;
        m0 = n0;  m1 = n1;
        float2 s;
        s.x = (n0 > THRESH) ? 1.0f : 0.0f;
        s.y = (n1 > THRESH) ? 1.0f : 0.0f;
        __stcs(&op[(size_t)t * stride2], s);
    }

    // ---- tail: scan + fused readout accumulation ----
    const float va = W2[h];                  // o=0 weight for h
    const float vb = W2[h + 1];              // o=0 weight for h+1
    const float wa = W2[H_DIM + h];          // o=1 weight for h
    const float wb = W2[H_DIM + h + 1];      // o=1 weight for h+1

    float acc[TAIL][OUT_DIM];
#pragma unroll
    for (int tt = 0; tt < TAIL; ++tt) {
        const int t = T_MAIN + tt;
        const float x0 = xs[3 * t + 0];
        const float x1 = xs[3 * t + 1];
        const float x2 = xs[3 * t + 2];
        float c0 = fmaf(x2, w02, fmaf(x1, w01, x0 * w00));
        float c1 = fmaf(x2, w12, fmaf(x1, w11, x0 * w10));
        float n0 = fmaf(BETA, m0, c0);  n0 = (m0 > THRESH) ? 0.0f : n0;
        float n1 = fmaf(BETA, m1, c1);  n1 = (m1 > THRESH) ? 0.0f : n1;
        m0 = n0;  m1 = n1;
        float2 s;
        s.x = (n0 > THRESH) ? 1.0f : 0.0f;
        s.y = (n1 > THRESH) ? 1.0f : 0.0f;
        __stcs(&op[(size_t)t * stride2], s);
        acc[tt][0] = fmaf(s.y, vb, s.x * va);
        acc[tt][1] = fmaf(s.y, wb, s.x * wa);
    }

    // ---- block reduction over H ----
#pragma unroll
    for (int tt = 0; tt < TAIL; ++tt) {
#pragma unroll
        for (int o = 0; o < OUT_DIM; ++o) {
            float v = acc[tt][o];
            v += __shfl_down_sync(0xFFFFFFFFu, v, 16);
            v += __shfl_down_sync(0xFFFFFFFFu, v, 8);
            v += __shfl_down_sync(0xFFFFFFFFu, v, 4);
            v += __shfl_down_sync(0xFFFFFFFFu, v, 2);
            v += __shfl_down_sync(0xFFFFFFFFu, v, 1);
            if (lane == 0) atomicAdd(&sums[tt * OUT_DIM + o], v);
        }
    }
    __syncthreads();

    if (tid < OUT_DIM) {
        float a = 0.0f;
#pragma unroll
        for (int tt = 0; tt < TAIL; ++tt) {
            const float z = sums[tt * OUT_DIM + tid];
            a += 1.0f / (1.0f + __expf(-z));
        }
        avg_out[b * OUT_DIM + tid] = a * (1.0f / (float)TAIL);
    }
}

extern "C" void kernel_launch(void* const* d_in, const int* in_sizes, int n_in,
                              void* d_out, int out_size)
{
    const float* x  = (const float*)d_in[0];   // [T, B, IN]
    const float* W1 = (const float*)d_in[1];   // [H, IN]
    const float* W2 = (const float*)d_in[2];   // [OUT, H]
    float* out = (float*)d_out;

    float* spk = out;                                          // [T, B, H]
    float* avg = out + (size_t)T_STEPS * BATCH * H_DIM;        // [B, OUT]

    snn_fused_kernel<<<BATCH, 256>>>(x, W1, W2, spk, avg);
}